// round 2
// baseline (speedup 1.0000x reference)
#include <cuda_runtime.h>
#include <math.h>

#define D_MODEL 768
#define NH      12
#define DHEAD   64
#define BATCH   8
#define SEQ     1024
#define TOK     (BATCH * SEQ)   // 8192

// Scratch (device globals — no runtime allocation allowed)
__device__ float g_q[TOK * D_MODEL];
__device__ float g_k[TOK * D_MODEL];
__device__ float g_v[TOK * D_MODEL];
__device__ float g_attn[TOK * D_MODEL];

// ---------------------------------------------------------------------------
// SGEMM + bias: C[M,N] = A[M,K] @ B[K,N] + bias[N]
// BMODE 0: B is plain row-major [K,N]
// BMODE 1: B is per-head stacked [H, D, DH]; column c maps to head c>>6, dim c&63
// 128x128 tile, BK=8, 256 threads, 8x8 micro-tile per thread.
// ---------------------------------------------------------------------------
template <int BMODE>
__global__ void __launch_bounds__(256)
sgemm_bias_kernel(const float* __restrict__ A, const float* __restrict__ B,
                  const float* __restrict__ bias, float* __restrict__ C,
                  int M, int N, int K) {
    __shared__ float As[8][129];
    __shared__ float Bs[8][129];

    const int tid = threadIdx.x;
    const int tx = tid & 15;      // 0..15 -> column group
    const int ty = tid >> 4;      // 0..15 -> row group
    const int m0 = blockIdx.y * 128;
    const int n0 = blockIdx.x * 128;

    float acc[8][8];
#pragma unroll
    for (int i = 0; i < 8; i++)
#pragma unroll
        for (int j = 0; j < 8; j++) acc[i][j] = 0.0f;

    for (int k0 = 0; k0 < K; k0 += 8) {
        // Load A tile: 128x8 (1024 elems / 256 threads = 4 each)
#pragma unroll
        for (int i = 0; i < 4; i++) {
            int idx = tid + i * 256;
            int m = idx >> 3;
            int kk = idx & 7;
            As[kk][m] = A[(size_t)(m0 + m) * K + (k0 + kk)];
        }
        // Load B tile: 8x128
#pragma unroll
        for (int i = 0; i < 4; i++) {
            int idx = tid + i * 256;
            int kk = idx >> 7;
            int n = idx & 127;
            int c = n0 + n;
            if (BMODE == 0) {
                Bs[kk][n] = B[(size_t)(k0 + kk) * N + c];
            } else {
                // per-head weights [H, D, DH]
                Bs[kk][n] = B[(size_t)(c >> 6) * (D_MODEL * DHEAD)
                              + (size_t)(k0 + kk) * DHEAD + (c & 63)];
            }
        }
        __syncthreads();

#pragma unroll
        for (int kk = 0; kk < 8; kk++) {
            float a[8], b[8];
#pragma unroll
            for (int i = 0; i < 8; i++) a[i] = As[kk][ty * 8 + i];
#pragma unroll
            for (int j = 0; j < 8; j++) b[j] = Bs[kk][tx * 8 + j];
#pragma unroll
            for (int i = 0; i < 8; i++)
#pragma unroll
                for (int j = 0; j < 8; j++) acc[i][j] += a[i] * b[j];
        }
        __syncthreads();
    }

#pragma unroll
    for (int i = 0; i < 8; i++) {
        int m = m0 + ty * 8 + i;
#pragma unroll
        for (int j = 0; j < 8; j++) {
            int n = n0 + tx * 8 + j;
            C[(size_t)m * N + n] = acc[i][j] + bias[n];
        }
    }
}

// ---------------------------------------------------------------------------
// Flash-attention style kernel.
// Q/K/V stored as [B, S, H*DH] (row stride D_MODEL, head slice at h*DH).
// Grid: (SEQ/64, B*NH). Block: 256 threads (16x16), each thread owns a
// 4-row x 4-col patch of the 64x64 score tile and a 4-row x 4-dim patch of O.
// Online softmax with warp-shuffle reductions across the 16-lane tx group.
// ---------------------------------------------------------------------------
__global__ void __launch_bounds__(256)
attention_kernel(const float* __restrict__ Q, const float* __restrict__ K,
                 const float* __restrict__ V, float* __restrict__ O) {
    extern __shared__ float smem[];
    float* Qs = smem;               // 64 x 65
    float* Ks = Qs + 64 * 65;       // 64 x 65
    float* Vs = Ks + 64 * 65;       // 64 x 65
    float* Ps = Vs + 64 * 65;       // 64 x 65

    const int tid = threadIdx.x;
    const int tx = tid & 15;
    const int ty = tid >> 4;
    const int bh = blockIdx.y;
    const int b = bh / NH;
    const int h = bh % NH;
    const size_t base = (size_t)b * SEQ * D_MODEL + (size_t)h * DHEAD;
    const int q0 = blockIdx.x * 64;

    // Load Q tile, pre-scaled by 1/sqrt(DH) = 0.125
    for (int i = tid; i < 64 * 64; i += 256) {
        int r = i >> 6, e = i & 63;
        Qs[r * 65 + e] = Q[base + (size_t)(q0 + r) * D_MODEL + e] * 0.125f;
    }
    __syncthreads();

    float m_i[4], l_i[4], o_acc[4][4];
#pragma unroll
    for (int i = 0; i < 4; i++) {
        m_i[i] = -1e30f;
        l_i[i] = 0.0f;
#pragma unroll
        for (int j = 0; j < 4; j++) o_acc[i][j] = 0.0f;
    }

    for (int kt = 0; kt < SEQ; kt += 64) {
        // Load K and V tiles
        for (int i = tid; i < 64 * 64; i += 256) {
            int r = i >> 6, e = i & 63;
            Ks[r * 65 + e] = K[base + (size_t)(kt + r) * D_MODEL + e];
            Vs[r * 65 + e] = V[base + (size_t)(kt + r) * D_MODEL + e];
        }
        __syncthreads();

        // S = Q K^T  (each thread: 4x4 patch, rows 4*ty.., cols 4*tx..)
        float s[4][4];
#pragma unroll
        for (int i = 0; i < 4; i++)
#pragma unroll
            for (int j = 0; j < 4; j++) s[i][j] = 0.0f;

        for (int e = 0; e < 64; e++) {
            float qv[4], kv[4];
#pragma unroll
            for (int i = 0; i < 4; i++) qv[i] = Qs[(ty * 4 + i) * 65 + e];
#pragma unroll
            for (int j = 0; j < 4; j++) kv[j] = Ks[(tx * 4 + j) * 65 + e];
#pragma unroll
            for (int i = 0; i < 4; i++)
#pragma unroll
                for (int j = 0; j < 4; j++) s[i][j] += qv[i] * kv[j];
        }
        __syncthreads();   // everyone done reading Ks before Ps overwrite race checks

        // Online softmax per row (reduce across the 16 tx lanes; lanes with the
        // same ty are contiguous within a 16-lane half-warp, so xor<16 stays put)
#pragma unroll
        for (int i = 0; i < 4; i++) {
            float tm = fmaxf(fmaxf(s[i][0], s[i][1]), fmaxf(s[i][2], s[i][3]));
#pragma unroll
            for (int off = 1; off < 16; off <<= 1)
                tm = fmaxf(tm, __shfl_xor_sync(0xffffffffu, tm, off));

            float newm = fmaxf(m_i[i], tm);
            float fac = __expf(m_i[i] - newm);
            m_i[i] = newm;

            float ts = 0.0f;
#pragma unroll
            for (int j = 0; j < 4; j++) {
                s[i][j] = __expf(s[i][j] - newm);
                ts += s[i][j];
            }
#pragma unroll
            for (int off = 1; off < 16; off <<= 1)
                ts += __shfl_xor_sync(0xffffffffu, ts, off);

            l_i[i] = l_i[i] * fac + ts;
#pragma unroll
            for (int d = 0; d < 4; d++) o_acc[i][d] *= fac;

            // stage P for the PV GEMM
#pragma unroll
            for (int j = 0; j < 4; j++)
                Ps[(ty * 4 + i) * 65 + (tx * 4 + j)] = s[i][j];
        }
        __syncthreads();

        // O += P @ V   (thread owns rows 4*ty.., dims 4*tx..)
        for (int jj = 0; jj < 64; jj++) {
            float vv[4];
#pragma unroll
            for (int d = 0; d < 4; d++) vv[d] = Vs[jj * 65 + tx * 4 + d];
#pragma unroll
            for (int i = 0; i < 4; i++) {
                float p = Ps[(ty * 4 + i) * 65 + jj];
#pragma unroll
                for (int d = 0; d < 4; d++) o_acc[i][d] += p * vv[d];
            }
        }
        __syncthreads();
    }

    // Finalize: divide by l, write to [B, S, H*DH]
#pragma unroll
    for (int i = 0; i < 4; i++) {
        float inv = 1.0f / l_i[i];
        int r = q0 + ty * 4 + i;
#pragma unroll
        for (int d = 0; d < 4; d++)
            O[base + (size_t)r * D_MODEL + (tx * 4 + d)] = o_acc[i][d] * inv;
    }
}

// ---------------------------------------------------------------------------
extern "C" void kernel_launch(void* const* d_in, const int* in_sizes, int n_in,
                              void* d_out, int out_size) {
    (void)in_sizes; (void)n_in; (void)out_size;
    const float* x  = (const float*)d_in[0];
    const float* Wq = (const float*)d_in[1];
    const float* bq = (const float*)d_in[2];
    const float* Wk = (const float*)d_in[3];
    const float* bk = (const float*)d_in[4];
    const float* Wv = (const float*)d_in[5];
    const float* bv = (const float*)d_in[6];
    const float* Wo = (const float*)d_in[7];
    const float* bo = (const float*)d_in[8];
    float* out = (float*)d_out;

    float *q, *k, *v, *attn;
    cudaGetSymbolAddress((void**)&q, g_q);
    cudaGetSymbolAddress((void**)&k, g_k);
    cudaGetSymbolAddress((void**)&v, g_v);
    cudaGetSymbolAddress((void**)&attn, g_attn);

    const int smem_attn = 4 * 64 * 65 * (int)sizeof(float);  // 66560 B
    cudaFuncSetAttribute(attention_kernel,
                         cudaFuncAttributeMaxDynamicSharedMemorySize, smem_attn);

    // QKV projections: [8192,768] @ per-head [H,D,DH] -> [8192,768]
    dim3 gemm_grid(D_MODEL / 128, TOK / 128);   // (6, 64)
    sgemm_bias_kernel<1><<<gemm_grid, 256>>>(x, Wq, bq, q, TOK, D_MODEL, D_MODEL);
    sgemm_bias_kernel<1><<<gemm_grid, 256>>>(x, Wk, bk, k, TOK, D_MODEL, D_MODEL);
    sgemm_bias_kernel<1><<<gemm_grid, 256>>>(x, Wv, bv, v, TOK, D_MODEL, D_MODEL);

    // Attention
    dim3 attn_grid(SEQ / 64, BATCH * NH);       // (16, 96)
    attention_kernel<<<attn_grid, 256, smem_attn>>>(q, k, v, attn);

    // Output projection: [8192,768] @ [768,768] + bias -> d_out
    sgemm_bias_kernel<0><<<gemm_grid, 256>>>(attn, Wo, bo, out, TOK, D_MODEL, D_MODEL);
}

// round 4
// speedup vs baseline: 1.8690x; 1.8690x over previous
#include <cuda_runtime.h>
#include <math.h>
#include <cstdint>

#define D_MODEL 768
#define NH      12
#define DHEAD   64
#define BATCH   8
#define SEQ     1024
#define TOK     (BATCH * SEQ)   // 8192

// Scratch (device globals — no runtime allocation allowed)
__device__ float g_q[TOK * D_MODEL];
__device__ float g_k[TOK * D_MODEL];
__device__ float g_v[TOK * D_MODEL];
__device__ float g_attn[TOK * D_MODEL];

__device__ __forceinline__ float to_tf32(float x) {
    float r;
    asm("cvt.rna.tf32.f32 %0, %1;" : "=f"(r) : "f"(x));
    return r;
}

// d += a @ b  (m16n8k8 tf32, fp32 accum)
__device__ __forceinline__ void mma_tf32(float* c, const float* a, const float* b) {
    asm volatile(
        "mma.sync.aligned.m16n8k8.row.col.f32.tf32.tf32.f32 "
        "{%0,%1,%2,%3}, {%4,%5,%6,%7}, {%8,%9}, {%0,%1,%2,%3};"
        : "+f"(c[0]), "+f"(c[1]), "+f"(c[2]), "+f"(c[3])
        : "r"(__float_as_uint(a[0])), "r"(__float_as_uint(a[1])),
          "r"(__float_as_uint(a[2])), "r"(__float_as_uint(a[3])),
          "r"(__float_as_uint(b[0])), "r"(__float_as_uint(b[1])));
}

// ===========================================================================
// tf32 tensor-core GEMM + bias: C[M,N] = A[M,768] @ B(768,N) + bias[N]
// BMODE 0: B row-major [K, N]            (Wo)
// BMODE 1: B per-head stacked [H, D, DH]  (Wq/Wk/Wv); col c -> head c>>6, dim c&63
// CTA tile 128x128, BK=16, 256 threads (8 warps, 4x2), warp tile 32x64.
// Double-buffered smem, reg-staged global loads.
// ===========================================================================
#define BK  16
#define NIT (D_MODEL / BK)   // 48
#define AS_STRIDE 20         // 16 cols + 4 pad  (frag banks: 20*gid%32 distinct)
#define BS_STRIDE 136        // 128 cols + 8 pad (frag banks: 8*tig+gid distinct)

template <int BMODE>
__global__ void __launch_bounds__(256)
mma_gemm_kernel(const float* __restrict__ A, const float* __restrict__ B,
                const float* __restrict__ bias, float* __restrict__ C) {
    __shared__ __align__(16) float As[2][128][AS_STRIDE];
    __shared__ __align__(16) float Bs[2][BK][BS_STRIDE];

    const int tid = threadIdx.x;
    const int lane = tid & 31;
    const int wid = tid >> 5;
    const int gid = lane >> 2;     // groupID (0..7)
    const int tig = lane & 3;      // threadID_in_group (0..3)
    const int warp_m = wid & 3;    // 0..3  -> 32-row band
    const int warp_n = wid >> 2;   // 0..1  -> 64-col band
    const int m0 = blockIdx.y * 128;
    const int n0 = blockIdx.x * 128;

    // --- staging index math ---
    // A tile: 128x16 floats = 512 float4; thread handles float4 ids {tid, tid+256}
    // id -> row = id>>2, col4 = id&3
    const int a_row0 = tid >> 2;          // id = tid
    const int a_col0 = (tid & 3) * 4;
    const int a_row1 = (tid + 256) >> 2;  // id = tid+256
    const int a_col1 = a_col0;            // (id&3) unchanged by +256
    // B tile: 16x128 floats = 512 float4; id -> krow = id>>5, col4 = id&31
    const int b_kr0 = tid >> 5;
    const int b_c0 = (tid & 31) * 4;
    const int b_kr1 = (tid + 256) >> 5;
    const int b_c1 = b_c0;

    float acc[2][8][4];
#pragma unroll
    for (int mt = 0; mt < 2; mt++)
#pragma unroll
        for (int nt = 0; nt < 8; nt++)
#pragma unroll
            for (int i = 0; i < 4; i++) acc[mt][nt][i] = 0.0f;

    float4 ra0, ra1, rb0, rb1;

    // ---- global load helper (as lambdas via macros) ----
#define LDG_TILE(k0)                                                          \
    do {                                                                      \
        ra0 = *(const float4*)&A[(size_t)(m0 + a_row0) * D_MODEL + (k0) + a_col0]; \
        ra1 = *(const float4*)&A[(size_t)(m0 + a_row1) * D_MODEL + (k0) + a_col1]; \
        if (BMODE == 0) {                                                     \
            rb0 = *(const float4*)&B[(size_t)((k0) + b_kr0) * D_MODEL + n0 + b_c0]; \
            rb1 = *(const float4*)&B[(size_t)((k0) + b_kr1) * D_MODEL + n0 + b_c1]; \
        } else {                                                              \
            int c0 = n0 + b_c0, c1 = n0 + b_c1;                               \
            rb0 = *(const float4*)&B[((size_t)(c0 >> 6) * D_MODEL + (k0) + b_kr0) * DHEAD + (c0 & 63)]; \
            rb1 = *(const float4*)&B[((size_t)(c1 >> 6) * D_MODEL + (k0) + b_kr1) * DHEAD + (c1 & 63)]; \
        }                                                                     \
    } while (0)

#define STS_TILE(buf)                                                         \
    do {                                                                      \
        float4 t;                                                             \
        t.x = to_tf32(ra0.x); t.y = to_tf32(ra0.y);                           \
        t.z = to_tf32(ra0.z); t.w = to_tf32(ra0.w);                           \
        *(float4*)&As[buf][a_row0][a_col0] = t;                               \
        t.x = to_tf32(ra1.x); t.y = to_tf32(ra1.y);                           \
        t.z = to_tf32(ra1.z); t.w = to_tf32(ra1.w);                           \
        *(float4*)&As[buf][a_row1][a_col1] = t;                               \
        t.x = to_tf32(rb0.x); t.y = to_tf32(rb0.y);                           \
        t.z = to_tf32(rb0.z); t.w = to_tf32(rb0.w);                           \
        *(float4*)&Bs[buf][b_kr0][b_c0] = t;                                  \
        t.x = to_tf32(rb1.x); t.y = to_tf32(rb1.y);                           \
        t.z = to_tf32(rb1.z); t.w = to_tf32(rb1.w);                           \
        *(float4*)&Bs[buf][b_kr1][b_c1] = t;                                  \
    } while (0)

    // prologue: tile 0 -> buf 0
    LDG_TILE(0);
    STS_TILE(0);
    __syncthreads();

#pragma unroll 1
    for (int it = 0; it < NIT; it++) {
        const int buf = it & 1;
        if (it + 1 < NIT) LDG_TILE((it + 1) * BK);

        // compute 2 k-steps of 8 from smem buf
#pragma unroll
        for (int ks = 0; ks < 2; ks++) {
            const int kb = ks * 8;
            float a[2][4];
#pragma unroll
            for (int mt = 0; mt < 2; mt++) {
                const int r = warp_m * 32 + mt * 16 + gid;
                a[mt][0] = As[buf][r][kb + tig];
                a[mt][1] = As[buf][r + 8][kb + tig];
                a[mt][2] = As[buf][r][kb + tig + 4];
                a[mt][3] = As[buf][r + 8][kb + tig + 4];
            }
            float b[8][2];
#pragma unroll
            for (int nt = 0; nt < 8; nt++) {
                const int cn = warp_n * 64 + nt * 8 + gid;
                b[nt][0] = Bs[buf][kb + tig][cn];
                b[nt][1] = Bs[buf][kb + tig + 4][cn];
            }
#pragma unroll
            for (int mt = 0; mt < 2; mt++)
#pragma unroll
                for (int nt = 0; nt < 8; nt++)
                    mma_tf32(acc[mt][nt], a[mt], b[nt]);
        }

        if (it + 1 < NIT) STS_TILE(buf ^ 1);
        __syncthreads();
    }

    // ---- epilogue: fragment-direct stores + bias ----
#pragma unroll
    for (int nt = 0; nt < 8; nt++) {
        const int cn = n0 + warp_n * 64 + nt * 8 + 2 * tig;
        const float2 bb = *(const float2*)&bias[cn];
#pragma unroll
        for (int mt = 0; mt < 2; mt++) {
            const int r = m0 + warp_m * 32 + mt * 16 + gid;
            float2 v0 = make_float2(acc[mt][nt][0] + bb.x, acc[mt][nt][1] + bb.y);
            float2 v1 = make_float2(acc[mt][nt][2] + bb.x, acc[mt][nt][3] + bb.y);
            *(float2*)&C[(size_t)r * D_MODEL + cn] = v0;
            *(float2*)&C[(size_t)(r + 8) * D_MODEL + cn] = v1;
        }
    }
#undef LDG_TILE
#undef STS_TILE
}

// ---------------------------------------------------------------------------
// Flash-attention style kernel (UNCHANGED from the passing round-1 version).
// ---------------------------------------------------------------------------
__global__ void __launch_bounds__(256)
attention_kernel(const float* __restrict__ Q, const float* __restrict__ K,
                 const float* __restrict__ V, float* __restrict__ O) {
    extern __shared__ float smem[];
    float* Qs = smem;               // 64 x 65
    float* Ks = Qs + 64 * 65;       // 64 x 65
    float* Vs = Ks + 64 * 65;       // 64 x 65
    float* Ps = Vs + 64 * 65;       // 64 x 65

    const int tid = threadIdx.x;
    const int tx = tid & 15;
    const int ty = tid >> 4;
    const int bh = blockIdx.y;
    const int b = bh / NH;
    const int h = bh % NH;
    const size_t base = (size_t)b * SEQ * D_MODEL + (size_t)h * DHEAD;
    const int q0 = blockIdx.x * 64;

    for (int i = tid; i < 64 * 64; i += 256) {
        int r = i >> 6, e = i & 63;
        Qs[r * 65 + e] = Q[base + (size_t)(q0 + r) * D_MODEL + e] * 0.125f;
    }
    __syncthreads();

    float m_i[4], l_i[4], o_acc[4][4];
#pragma unroll
    for (int i = 0; i < 4; i++) {
        m_i[i] = -1e30f;
        l_i[i] = 0.0f;
#pragma unroll
        for (int j = 0; j < 4; j++) o_acc[i][j] = 0.0f;
    }

    for (int kt = 0; kt < SEQ; kt += 64) {
        for (int i = tid; i < 64 * 64; i += 256) {
            int r = i >> 6, e = i & 63;
            Ks[r * 65 + e] = K[base + (size_t)(kt + r) * D_MODEL + e];
            Vs[r * 65 + e] = V[base + (size_t)(kt + r) * D_MODEL + e];
        }
        __syncthreads();

        float s[4][4];
#pragma unroll
        for (int i = 0; i < 4; i++)
#pragma unroll
            for (int j = 0; j < 4; j++) s[i][j] = 0.0f;

        for (int e = 0; e < 64; e++) {
            float qv[4], kv[4];
#pragma unroll
            for (int i = 0; i < 4; i++) qv[i] = Qs[(ty * 4 + i) * 65 + e];
#pragma unroll
            for (int j = 0; j < 4; j++) kv[j] = Ks[(tx * 4 + j) * 65 + e];
#pragma unroll
            for (int i = 0; i < 4; i++)
#pragma unroll
                for (int j = 0; j < 4; j++) s[i][j] += qv[i] * kv[j];
        }
        __syncthreads();

#pragma unroll
        for (int i = 0; i < 4; i++) {
            float tm = fmaxf(fmaxf(s[i][0], s[i][1]), fmaxf(s[i][2], s[i][3]));
#pragma unroll
            for (int off = 1; off < 16; off <<= 1)
                tm = fmaxf(tm, __shfl_xor_sync(0xffffffffu, tm, off));

            float newm = fmaxf(m_i[i], tm);
            float fac = __expf(m_i[i] - newm);
            m_i[i] = newm;

            float ts = 0.0f;
#pragma unroll
            for (int j = 0; j < 4; j++) {
                s[i][j] = __expf(s[i][j] - newm);
                ts += s[i][j];
            }
#pragma unroll
            for (int off = 1; off < 16; off <<= 1)
                ts += __shfl_xor_sync(0xffffffffu, ts, off);

            l_i[i] = l_i[i] * fac + ts;
#pragma unroll
            for (int d = 0; d < 4; d++) o_acc[i][d] *= fac;

#pragma unroll
            for (int j = 0; j < 4; j++)
                Ps[(ty * 4 + i) * 65 + (tx * 4 + j)] = s[i][j];
        }
        __syncthreads();

        for (int jj = 0; jj < 64; jj++) {
            float vv[4];
#pragma unroll
            for (int d = 0; d < 4; d++) vv[d] = Vs[jj * 65 + tx * 4 + d];
#pragma unroll
            for (int i = 0; i < 4; i++) {
                float p = Ps[(ty * 4 + i) * 65 + jj];
#pragma unroll
                for (int d = 0; d < 4; d++) o_acc[i][d] += p * vv[d];
            }
        }
        __syncthreads();
    }

#pragma unroll
    for (int i = 0; i < 4; i++) {
        float inv = 1.0f / l_i[i];
        int r = q0 + ty * 4 + i;
#pragma unroll
        for (int d = 0; d < 4; d++)
            O[base + (size_t)r * D_MODEL + (tx * 4 + d)] = o_acc[i][d] * inv;
    }
}

// ---------------------------------------------------------------------------
extern "C" void kernel_launch(void* const* d_in, const int* in_sizes, int n_in,
                              void* d_out, int out_size) {
    (void)in_sizes; (void)n_in; (void)out_size;
    const float* x  = (const float*)d_in[0];
    const float* Wq = (const float*)d_in[1];
    const float* bq = (const float*)d_in[2];
    const float* Wk = (const float*)d_in[3];
    const float* bk = (const float*)d_in[4];
    const float* Wv = (const float*)d_in[5];
    const float* bv = (const float*)d_in[6];
    const float* Wo = (const float*)d_in[7];
    const float* bo = (const float*)d_in[8];
    float* out = (float*)d_out;

    float *q, *k, *v, *attn;
    cudaGetSymbolAddress((void**)&q, g_q);
    cudaGetSymbolAddress((void**)&k, g_k);
    cudaGetSymbolAddress((void**)&v, g_v);
    cudaGetSymbolAddress((void**)&attn, g_attn);

    const int smem_attn = 4 * 64 * 65 * (int)sizeof(float);  // 66560 B
    cudaFuncSetAttribute(attention_kernel,
                         cudaFuncAttributeMaxDynamicSharedMemorySize, smem_attn);

    // QKV projections via tensor-core tf32 mma.sync
    dim3 gemm_grid(D_MODEL / 128, TOK / 128);   // (6, 64)
    mma_gemm_kernel<1><<<gemm_grid, 256>>>(x, Wq, bq, q);
    mma_gemm_kernel<1><<<gemm_grid, 256>>>(x, Wk, bk, k);
    mma_gemm_kernel<1><<<gemm_grid, 256>>>(x, Wv, bv, v);

    // Attention (unchanged)
    dim3 attn_grid(SEQ / 64, BATCH * NH);       // (16, 96)
    attention_kernel<<<attn_grid, 256, smem_attn>>>(q, k, v, attn);

    // Output projection via tensor-core tf32 mma.sync
    mma_gemm_kernel<0><<<gemm_grid, 256>>>(attn, Wo, bo, out);
}

// round 7
// speedup vs baseline: 3.7973x; 2.0317x over previous
#include <cuda_runtime.h>
#include <math.h>
#include <cstdint>

#define D_MODEL 768
#define NH      12
#define DHEAD   64
#define BATCH   8
#define SEQ     1024
#define TOK     (BATCH * SEQ)   // 8192

// Scratch (device globals — no runtime allocation allowed)
__device__ float g_q[TOK * D_MODEL];
__device__ float g_k[TOK * D_MODEL];
__device__ float g_v[TOK * D_MODEL];
__device__ float g_attn[TOK * D_MODEL];

__device__ __forceinline__ float to_tf32(float x) {
    float r;
    asm("cvt.rna.tf32.f32 %0, %1;" : "=f"(r) : "f"(x));
    return r;
}

__device__ __forceinline__ uint32_t smem_u32(const void* p) {
    uint32_t a;
    asm("{ .reg .u64 t; cvta.to.shared.u64 t, %1; cvt.u32.u64 %0, t; }"
        : "=r"(a) : "l"(p));
    return a;
}

// c += a @ b  (m16n8k8 tf32, fp32 accum)
__device__ __forceinline__ void mma_tf32(float* c, const float* a, float b0, float b1) {
    asm volatile(
        "mma.sync.aligned.m16n8k8.row.col.f32.tf32.tf32.f32 "
        "{%0,%1,%2,%3}, {%4,%5,%6,%7}, {%8,%9}, {%0,%1,%2,%3};"
        : "+f"(c[0]), "+f"(c[1]), "+f"(c[2]), "+f"(c[3])
        : "r"(__float_as_uint(a[0])), "r"(__float_as_uint(a[1])),
          "r"(__float_as_uint(a[2])), "r"(__float_as_uint(a[3])),
          "r"(__float_as_uint(b0)), "r"(__float_as_uint(b1)));
}

#define CP_ASYNC16(saddr, gptr) \
    asm volatile("cp.async.cg.shared.global [%0], [%1], 16;" \
                 :: "r"(saddr), "l"(gptr) : "memory")
#define CP_COMMIT() asm volatile("cp.async.commit_group;" ::: "memory")
#define CP_WAIT(n)  asm volatile("cp.async.wait_group %0;" :: "n"(n) : "memory")

// ===========================================================================
// tf32 tensor-core GEMM + bias: C[M,N] = A[M,768] @ B(768,N) + bias[N]
// BMODE 0: B row-major [K, N]            (Wo)
// BMODE 1: B per-head stacked [H, D, DH]  (Wq/Wk/Wv)
// ROUND 1: round output to tf32 (so downstream mma reads are lossless)
// ===========================================================================
#define BK  16
#define NIT (D_MODEL / BK)   // 48
#define AS_STRIDE 20
#define BS_STRIDE 136

template <int BMODE, int ROUND>
__global__ void __launch_bounds__(256)
mma_gemm_kernel(const float* __restrict__ A, const float* __restrict__ B,
                const float* __restrict__ bias, float* __restrict__ C) {
    __shared__ __align__(16) float As[2][128][AS_STRIDE];
    __shared__ __align__(16) float Bs[2][BK][BS_STRIDE];

    const int tid = threadIdx.x;
    const int lane = tid & 31;
    const int wid = tid >> 5;
    const int gid = lane >> 2;
    const int tig = lane & 3;
    const int warp_m = wid & 3;
    const int warp_n = wid >> 2;
    const int m0 = blockIdx.y * 128;
    const int n0 = blockIdx.x * 128;

    const int a_row0 = tid >> 2;
    const int a_col0 = (tid & 3) * 4;
    const int a_row1 = (tid + 256) >> 2;
    const int a_col1 = a_col0;
    const int b_kr0 = tid >> 5;
    const int b_c0 = (tid & 31) * 4;
    const int b_kr1 = (tid + 256) >> 5;
    const int b_c1 = b_c0;

    float acc[2][8][4];
#pragma unroll
    for (int mt = 0; mt < 2; mt++)
#pragma unroll
        for (int nt = 0; nt < 8; nt++)
#pragma unroll
            for (int i = 0; i < 4; i++) acc[mt][nt][i] = 0.0f;

    float4 ra0, ra1, rb0, rb1;

#define LDG_TILE(k0)                                                          \
    do {                                                                      \
        ra0 = *(const float4*)&A[(size_t)(m0 + a_row0) * D_MODEL + (k0) + a_col0]; \
        ra1 = *(const float4*)&A[(size_t)(m0 + a_row1) * D_MODEL + (k0) + a_col1]; \
        if (BMODE == 0) {                                                     \
            rb0 = *(const float4*)&B[(size_t)((k0) + b_kr0) * D_MODEL + n0 + b_c0]; \
            rb1 = *(const float4*)&B[(size_t)((k0) + b_kr1) * D_MODEL + n0 + b_c1]; \
        } else {                                                              \
            int c0 = n0 + b_c0, c1 = n0 + b_c1;                               \
            rb0 = *(const float4*)&B[((size_t)(c0 >> 6) * D_MODEL + (k0) + b_kr0) * DHEAD + (c0 & 63)]; \
            rb1 = *(const float4*)&B[((size_t)(c1 >> 6) * D_MODEL + (k0) + b_kr1) * DHEAD + (c1 & 63)]; \
        }                                                                     \
    } while (0)

#define STS_TILE(buf)                                                         \
    do {                                                                      \
        float4 t;                                                             \
        t.x = to_tf32(ra0.x); t.y = to_tf32(ra0.y);                           \
        t.z = to_tf32(ra0.z); t.w = to_tf32(ra0.w);                           \
        *(float4*)&As[buf][a_row0][a_col0] = t;                               \
        t.x = to_tf32(ra1.x); t.y = to_tf32(ra1.y);                           \
        t.z = to_tf32(ra1.z); t.w = to_tf32(ra1.w);                           \
        *(float4*)&As[buf][a_row1][a_col1] = t;                               \
        t.x = to_tf32(rb0.x); t.y = to_tf32(rb0.y);                           \
        t.z = to_tf32(rb0.z); t.w = to_tf32(rb0.w);                           \
        *(float4*)&Bs[buf][b_kr0][b_c0] = t;                                  \
        t.x = to_tf32(rb1.x); t.y = to_tf32(rb1.y);                           \
        t.z = to_tf32(rb1.z); t.w = to_tf32(rb1.w);                           \
        *(float4*)&Bs[buf][b_kr1][b_c1] = t;                                  \
    } while (0)

    LDG_TILE(0);
    STS_TILE(0);
    __syncthreads();

#pragma unroll 1
    for (int it = 0; it < NIT; it++) {
        const int buf = it & 1;
        if (it + 1 < NIT) LDG_TILE((it + 1) * BK);

#pragma unroll
        for (int ks = 0; ks < 2; ks++) {
            const int kb = ks * 8;
            float a[2][4];
#pragma unroll
            for (int mt = 0; mt < 2; mt++) {
                const int r = warp_m * 32 + mt * 16 + gid;
                a[mt][0] = As[buf][r][kb + tig];
                a[mt][1] = As[buf][r + 8][kb + tig];
                a[mt][2] = As[buf][r][kb + tig + 4];
                a[mt][3] = As[buf][r + 8][kb + tig + 4];
            }
            float b[8][2];
#pragma unroll
            for (int nt = 0; nt < 8; nt++) {
                const int cn = warp_n * 64 + nt * 8 + gid;
                b[nt][0] = Bs[buf][kb + tig][cn];
                b[nt][1] = Bs[buf][kb + tig + 4][cn];
            }
#pragma unroll
            for (int mt = 0; mt < 2; mt++)
#pragma unroll
                for (int nt = 0; nt < 8; nt++)
                    mma_tf32(acc[mt][nt], a[mt], b[nt][0], b[nt][1]);
        }

        if (it + 1 < NIT) STS_TILE(buf ^ 1);
        __syncthreads();
    }

#pragma unroll
    for (int nt = 0; nt < 8; nt++) {
        const int cn = n0 + warp_n * 64 + nt * 8 + 2 * tig;
        const float2 bb = *(const float2*)&bias[cn];
#pragma unroll
        for (int mt = 0; mt < 2; mt++) {
            const int r = m0 + warp_m * 32 + mt * 16 + gid;
            float2 v0 = make_float2(acc[mt][nt][0] + bb.x, acc[mt][nt][1] + bb.y);
            float2 v1 = make_float2(acc[mt][nt][2] + bb.x, acc[mt][nt][3] + bb.y);
            if (ROUND) {
                v0.x = to_tf32(v0.x); v0.y = to_tf32(v0.y);
                v1.x = to_tf32(v1.x); v1.y = to_tf32(v1.y);
            }
            *(float2*)&C[(size_t)r * D_MODEL + cn] = v0;
            *(float2*)&C[(size_t)(r + 8) * D_MODEL + cn] = v1;
        }
    }
#undef LDG_TILE
#undef STS_TILE
}

// ===========================================================================
// Tensor-core flash attention (tf32 mma.sync).
// CTA: 128 query rows of one (b,h). 256 threads = 8 warps, warp owns 16 rows.
// K/V tiles 64x64, double-buffered via cp.async.
// K stride 68 (QK^T B-frag reads conflict-free: (4*gid+tig)%32 distinct).
// V stride 72 (PV   B-frag reads conflict-free: (8*tig+8*nt+gid)%32 distinct).
// ===========================================================================
#define K_STRIDE 68
#define V_STRIDE 72
#define PS_STRIDE 76            // (12*gid+tig) mod 32 distinct -> conflict-free
#define KBUF     (64 * K_STRIDE)
#define VBUF     (64 * V_STRIDE)

__global__ void __launch_bounds__(256)
attention_kernel(const float* __restrict__ Q, const float* __restrict__ K,
                 const float* __restrict__ V, float* __restrict__ O) {
    extern __shared__ float smem[];
    float* Ks = smem;                    // [2][64][K_STRIDE]
    float* Vs = Ks + 2 * KBUF;           // [2][64][V_STRIDE]
    float* Ps = Vs + 2 * VBUF;           // [128][PS_STRIDE]  (also Q staging)

    const int tid = threadIdx.x;
    const int lane = tid & 31;
    const int wid = tid >> 5;
    const int gid = lane >> 2;
    const int tig = lane & 3;
    const int b = blockIdx.y / NH;
    const int h = blockIdx.y % NH;
    const size_t base = (size_t)b * SEQ * D_MODEL + (size_t)h * DHEAD;
    const int q0 = blockIdx.x * 128;

    const uint32_t smem_b = smem_u32(smem);
    const uint32_t ks_b = smem_b;
    const uint32_t vs_b = smem_b + 2 * KBUF * 4;
    const uint32_t ps_b = smem_b + (2 * KBUF + 2 * VBUF) * 4;

    // ---- async-copy Q tile into Ps (group 0) ----
#pragma unroll
    for (int i = 0; i < 8; i++) {
        const int id = tid + i * 256;          // 0..2047
        const int r = id >> 4, c4 = (id & 15) * 4;
        CP_ASYNC16(ps_b + (r * PS_STRIDE + c4) * 4,
                   Q + base + (size_t)(q0 + r) * D_MODEL + c4);
    }
    CP_COMMIT();

    // ---- async-copy K/V tile kt into buffer ----
#define LOAD_KV(kt, buf)                                                      \
    do {                                                                      \
        _Pragma("unroll")                                                     \
        for (int i = 0; i < 4; i++) {                                         \
            const int id = tid + i * 256;                                     \
            const int r = id >> 4, c4 = (id & 15) * 4;                        \
            const size_t go = base + (size_t)((kt) * 64 + r) * D_MODEL + c4;  \
            CP_ASYNC16(ks_b + ((buf) * KBUF + r * K_STRIDE + c4) * 4, K + go); \
            CP_ASYNC16(vs_b + ((buf) * VBUF + r * V_STRIDE + c4) * 4, V + go); \
        }                                                                     \
        CP_COMMIT();                                                          \
    } while (0)

    LOAD_KV(0, 0);
    LOAD_KV(1, 1);

    CP_WAIT(2);          // Q arrived
    __syncthreads();

    // ---- Q fragments (held for whole kernel), scale by 1/sqrt(64)=0.125 ----
    float qf[8][4];
    {
        const int r0 = (wid * 16 + gid) * PS_STRIDE;
        const int r1 = (wid * 16 + gid + 8) * PS_STRIDE;
#pragma unroll
        for (int kc = 0; kc < 8; kc++) {
            const int c = kc * 8 + tig;
            qf[kc][0] = to_tf32(0.125f * Ps[r0 + c]);
            qf[kc][1] = to_tf32(0.125f * Ps[r1 + c]);
            qf[kc][2] = to_tf32(0.125f * Ps[r0 + c + 4]);
            qf[kc][3] = to_tf32(0.125f * Ps[r1 + c + 4]);
        }
    }
    __syncthreads();     // all Q frag reads done before Ps is reused for P

    float o_acc[8][4];
#pragma unroll
    for (int nt = 0; nt < 8; nt++)
#pragma unroll
        for (int i = 0; i < 4; i++) o_acc[nt][i] = 0.0f;
    float m0r = -1e30f, m1r = -1e30f, l0r = 0.0f, l1r = 0.0f;

    float* Pw = Ps + wid * 16 * PS_STRIDE;

#pragma unroll 1
    for (int kt = 0; kt < 16; kt++) {
        if (kt < 15) { CP_WAIT(1); } else { CP_WAIT(0); }
        __syncthreads();
        const float* KsC = Ks + (kt & 1) * KBUF;
        const float* VsC = Vs + (kt & 1) * VBUF;

        // ---- S = Q K^T : warp computes 16x64 scores ----
        // B-frag: B[e][j] = K[j][e]  ->  KsC[(j)*K_STRIDE + e]
        float s[8][4];
#pragma unroll
        for (int nt = 0; nt < 8; nt++)
#pragma unroll
            for (int i = 0; i < 4; i++) s[nt][i] = 0.0f;

#pragma unroll
        for (int kc = 0; kc < 8; kc++) {
            float bk0[8], bk1[8];
#pragma unroll
            for (int nt = 0; nt < 8; nt++) {
                const int jr = (nt * 8 + gid) * K_STRIDE + kc * 8 + tig;
                bk0[nt] = KsC[jr];
                bk1[nt] = KsC[jr + 4];
            }
#pragma unroll
            for (int nt = 0; nt < 8; nt++)
                mma_tf32(s[nt], qf[kc], bk0[nt], bk1[nt]);
        }

        // ---- online softmax on fragments ----
        float mx0 = s[0][0], mx1 = s[0][2];
#pragma unroll
        for (int nt = 0; nt < 8; nt++) {
            mx0 = fmaxf(mx0, fmaxf(s[nt][0], s[nt][1]));
            mx1 = fmaxf(mx1, fmaxf(s[nt][2], s[nt][3]));
        }
        mx0 = fmaxf(mx0, __shfl_xor_sync(0xffffffffu, mx0, 1));
        mx0 = fmaxf(mx0, __shfl_xor_sync(0xffffffffu, mx0, 2));
        mx1 = fmaxf(mx1, __shfl_xor_sync(0xffffffffu, mx1, 1));
        mx1 = fmaxf(mx1, __shfl_xor_sync(0xffffffffu, mx1, 2));

        const float nm0 = fmaxf(m0r, mx0);
        const float nm1 = fmaxf(m1r, mx1);
        const float fac0 = __expf(m0r - nm0);
        const float fac1 = __expf(m1r - nm1);
        m0r = nm0; m1r = nm1;

        float sum0 = 0.0f, sum1 = 0.0f;
#pragma unroll
        for (int nt = 0; nt < 8; nt++) {
            s[nt][0] = __expf(s[nt][0] - nm0);
            s[nt][1] = __expf(s[nt][1] - nm0);
            s[nt][2] = __expf(s[nt][2] - nm1);
            s[nt][3] = __expf(s[nt][3] - nm1);
            sum0 += s[nt][0] + s[nt][1];
            sum1 += s[nt][2] + s[nt][3];
        }
        sum0 += __shfl_xor_sync(0xffffffffu, sum0, 1);
        sum0 += __shfl_xor_sync(0xffffffffu, sum0, 2);
        sum1 += __shfl_xor_sync(0xffffffffu, sum1, 1);
        sum1 += __shfl_xor_sync(0xffffffffu, sum1, 2);
        l0r = l0r * fac0 + sum0;
        l1r = l1r * fac1 + sum1;

#pragma unroll
        for (int nt = 0; nt < 8; nt++) {
            o_acc[nt][0] *= fac0; o_acc[nt][1] *= fac0;
            o_acc[nt][2] *= fac1; o_acc[nt][3] *= fac1;
        }

        // ---- stage P (warp-private) and re-fragment for PV ----
#pragma unroll
        for (int nt = 0; nt < 8; nt++) {
            const int c = nt * 8 + 2 * tig;
            *(float2*)&Pw[gid * PS_STRIDE + c] =
                make_float2(to_tf32(s[nt][0]), to_tf32(s[nt][1]));
            *(float2*)&Pw[(gid + 8) * PS_STRIDE + c] =
                make_float2(to_tf32(s[nt][2]), to_tf32(s[nt][3]));
        }
        __syncwarp();

        // ---- O += P @ V ----
        // B-frag: B[k=j][n=d] = V[j][d]  ->  VsC[(kc*8+tig)*V_STRIDE + nt*8+gid]
#pragma unroll
        for (int kc = 0; kc < 8; kc++) {
            float pa[4];
            const int c = kc * 8 + tig;
            pa[0] = Pw[gid * PS_STRIDE + c];
            pa[1] = Pw[(gid + 8) * PS_STRIDE + c];
            pa[2] = Pw[gid * PS_STRIDE + c + 4];
            pa[3] = Pw[(gid + 8) * PS_STRIDE + c + 4];
            float bv0[8], bv1[8];
            const int vr0 = (kc * 8 + tig) * V_STRIDE;
            const int vr1 = (kc * 8 + tig + 4) * V_STRIDE;
#pragma unroll
            for (int nt = 0; nt < 8; nt++) {
                bv0[nt] = VsC[vr0 + nt * 8 + gid];
                bv1[nt] = VsC[vr1 + nt * 8 + gid];
            }
#pragma unroll
            for (int nt = 0; nt < 8; nt++)
                mma_tf32(o_acc[nt], pa, bv0[nt], bv1[nt]);
        }

        __syncthreads();                 // all warps done with this KV buffer
        if (kt + 2 < 16) LOAD_KV(kt + 2, kt & 1);
    }

    // ---- finalize and store ----
    const float inv0 = 1.0f / l0r;
    const float inv1 = 1.0f / l1r;
    const int r0 = q0 + wid * 16 + gid;
#pragma unroll
    for (int nt = 0; nt < 8; nt++) {
        const int c = nt * 8 + 2 * tig;
        *(float2*)&O[base + (size_t)r0 * D_MODEL + c] =
            make_float2(o_acc[nt][0] * inv0, o_acc[nt][1] * inv0);
        *(float2*)&O[base + (size_t)(r0 + 8) * D_MODEL + c] =
            make_float2(o_acc[nt][2] * inv1, o_acc[nt][3] * inv1);
    }
#undef LOAD_KV
}

// ---------------------------------------------------------------------------
extern "C" void kernel_launch(void* const* d_in, const int* in_sizes, int n_in,
                              void* d_out, int out_size) {
    (void)in_sizes; (void)n_in; (void)out_size;
    const float* x  = (const float*)d_in[0];
    const float* Wq = (const float*)d_in[1];
    const float* bq = (const float*)d_in[2];
    const float* Wk = (const float*)d_in[3];
    const float* bk = (const float*)d_in[4];
    const float* Wv = (const float*)d_in[5];
    const float* bv = (const float*)d_in[6];
    const float* Wo = (const float*)d_in[7];
    const float* bo = (const float*)d_in[8];
    float* out = (float*)d_out;

    float *q, *k, *v, *attn;
    cudaGetSymbolAddress((void**)&q, g_q);
    cudaGetSymbolAddress((void**)&k, g_k);
    cudaGetSymbolAddress((void**)&v, g_v);
    cudaGetSymbolAddress((void**)&attn, g_attn);

    const int smem_attn =
        (2 * KBUF + 2 * VBUF + 128 * PS_STRIDE) * (int)sizeof(float); // 110592
    cudaFuncSetAttribute(attention_kernel,
                         cudaFuncAttributeMaxDynamicSharedMemorySize, smem_attn);

    // QKV projections (outputs rounded to tf32 for the attention mma path)
    dim3 gemm_grid(D_MODEL / 128, TOK / 128);   // (6, 64)
    mma_gemm_kernel<1, 1><<<gemm_grid, 256>>>(x, Wq, bq, q);
    mma_gemm_kernel<1, 1><<<gemm_grid, 256>>>(x, Wk, bk, k);
    mma_gemm_kernel<1, 1><<<gemm_grid, 256>>>(x, Wv, bv, v);

    // Tensor-core flash attention
    dim3 attn_grid(SEQ / 128, BATCH * NH);      // (8, 96)
    attention_kernel<<<attn_grid, 256, smem_attn>>>(q, k, v, attn);

    // Output projection (full fp32 output)
    mma_gemm_kernel<0, 0><<<gemm_grid, 256>>>(attn, Wo, bo, out);
}